// round 4
// baseline (speedup 1.0000x reference)
#include <cuda_runtime.h>

#define LRES     2048
#define NBATCH   8
#define KSEL     64
#define NBINS    64
#define D2CUT    49.0f          // 7 A cutoff: f(7) = 3e-6, dropped tail provably negligible
#define BINSCALE 1.30612245f    // NBINS / D2CUT
#define CANDCAP  288
#define BBCAP    64             // boundary-bin buffer (reuses hist row)
#define RPB      16
#define NTHREADS 512
#define FULLMASK 0xffffffffu

__device__ __forceinline__ unsigned warp_incl_scan(unsigned v, int lane) {
#pragma unroll
    for (int off = 1; off < 32; off <<= 1) {
        unsigned u = __shfl_up_sync(FULLMASK, v, off);
        if (lane >= off) v += u;
    }
    return v;
}

// f(d2) = WALL * softplus((R0 - r)/DELTA) * smoothstep_down(r; 8, 10)
__device__ __forceinline__ float pair_energy(float d2) {
    float r  = sqrtf(fmaxf(d2, 1e-12f));
    float t  = (r - 8.0f) * 0.5f;
    t        = fminf(fmaxf(t, 0.0f), 1.0f);
    float sw = 1.0f - t * t * (3.0f - 2.0f * t);
    float x  = (4.0f - r) * 5.0f;
    float sp = (x > 20.0f) ? x : log1pf(expf(x));
    return 10.0f * sp * sw;
}

__global__ void zero_out_kernel(float* out) {
    if (threadIdx.x < NBATCH) out[threadIdx.x] = 0.0f;
}

__global__ __launch_bounds__(NTHREADS)
void repulsion_kernel(const float* __restrict__ R, float* __restrict__ out) {
    __shared__ float2   sxy[LRES];            // 16384 B
    __shared__ float    sz [LRES];            //  8192 B
    __shared__ unsigned hist[RPB][NBINS];     //  4096 B (row reused as boundary-bin buffer)
    __shared__ float    cand[RPB][CANDCAP];   // 18432 B
    __shared__ float    warpsum[RPB];         // total 47168 B < 48 KB static

    const int blocksPerBatch = LRES / RPB;    // 128
    const int b     = blockIdx.x / blocksPerBatch;
    const int rbase = (blockIdx.x % blocksPerBatch) * RPB;
    const float* Rb = R + (size_t)b * LRES * 3;

    // stage coords (SoA: float2 xy + float z)
    for (int j = threadIdx.x; j < LRES; j += NTHREADS) {
        sxy[j] = make_float2(Rb[3 * j + 0], Rb[3 * j + 1]);
        sz[j]  = Rb[3 * j + 2];
    }
    for (int t = threadIdx.x; t < RPB * NBINS; t += NTHREADS)
        ((unsigned*)hist)[t] = 0;
    __syncthreads();

    const int warp = threadIdx.x >> 5;
    const int lane = threadIdx.x & 31;
    const unsigned lmask = (1u << lane) - 1u;
    const int i    = rbase + warp;
    const float2 pi = sxy[i];
    const float  zi = sz[i];

    // ---- fused pass: 64-bin histogram + compact all d2 < 49 candidates ----
    // 2-point ILP unroll; trip count uniform across lanes (LRES % 64 == 0).
    unsigned base = 0;
    for (int j0 = 0; j0 < LRES; j0 += 64) {
        int ja = j0 + lane;
        int jb = ja + 32;
        float2 pa = sxy[ja];  float za = sz[ja];
        float2 pb = sxy[jb];  float zb = sz[jb];

        float dxa = pa.x - pi.x, dya = pa.y - pi.y, dza = za - zi;
        float d2a = fmaf(dxa, dxa, fmaf(dya, dya, dza * dza));
        float dxb = pb.x - pi.x, dyb = pb.y - pi.y, dzb = zb - zi;
        float d2b = fmaf(dxb, dxb, fmaf(dyb, dyb, dzb * dzb));

        bool keepa = ((unsigned)(ja - i + 1) > 2u) && (d2a < D2CUT);   // |ja-i| >= 2
        bool keepb = ((unsigned)(jb - i + 1) > 2u) && (d2b < D2CUT);

        unsigned ma = __ballot_sync(FULLMASK, keepa);
        if (ma) {
            if (keepa) {
                int bin = min((int)(d2a * BINSCALE), NBINS - 1);
                atomicAdd(&hist[warp][bin], 1u);
                unsigned pos = base + __popc(ma & lmask);
                if (pos < CANDCAP) cand[warp][pos] = d2a;
            }
            base += __popc(ma);
        }
        unsigned mb = __ballot_sync(FULLMASK, keepb);
        if (mb) {
            if (keepb) {
                int bin = min((int)(d2b * BINSCALE), NBINS - 1);
                atomicAdd(&hist[warp][bin], 1u);
                unsigned pos = base + __popc(mb & lmask);
                if (pos < CANDCAP) cand[warp][pos] = d2b;
            }
            base += __popc(mb);
        }
    }
    __syncwarp();

    // ---- cumulative scan over 64 bins (2 chunks of 32) ----
    unsigned v0 = hist[warp][lane];
    unsigned v1 = hist[warp][lane + 32];
    unsigned c0 = warp_incl_scan(v0, lane);
    unsigned t0 = __shfl_sync(FULLMASK, c0, 31);
    unsigned c1 = warp_incl_scan(v1, lane) + t0;

    // first bin B with cum >= KSEL (NBINS-1 if none: keep everything)
    int B = NBINS - 1;
    {
        unsigned m0 = __ballot_sync(FULLMASK, c0 >= (unsigned)KSEL);
        if (m0) B = __ffs(m0) - 1;
        else {
            unsigned m1 = __ballot_sync(FULLMASK, c1 >= (unsigned)KSEL);
            if (m1) B = 32 + __ffs(m1) - 1;
        }
    }
    unsigned cumB = (B < 32) ? __shfl_sync(FULLMASK, c0, B) : __shfl_sync(FULLMASK, c1, B - 32);
    unsigned vB   = (B < 32) ? __shfl_sync(FULLMASK, v0, B) : __shfl_sync(FULLMASK, v1, B - 32);
    const int need = KSEL - (int)(cumB - vB);   // >= 1; may exceed vB (then keep whole bin)
    __syncwarp();                               // hist row consumed -> reusable

    // ---- epilogue pass over candidate buffer ----
    // bin < B : guaranteed top-64, accumulate f directly.
    // bin == B: compact into tiny buffer for exact boundary ranking.
    float* bb = (float*)hist[warp];
    const int n = (int)min(base, (unsigned)CANDCAP);
    unsigned bcnt = 0;
    float esum = 0.0f;
    for (int c0i = 0; c0i < n; c0i += 32) {
        int c = c0i + lane;
        bool inb = (c < n);
        float v = inb ? cand[warp][c] : 1e9f;
        int bin = min((int)(v * BINSCALE), NBINS - 1);   // identical expr to hot loop
        bool lt = inb && (bin < B);
        bool eq = inb && (bin == B);
        if (lt) esum += pair_energy(v);
        unsigned me = __ballot_sync(FULLMASK, eq);
        if (me) {
            if (eq) {
                unsigned pos = bcnt + __popc(me & lmask);
                if (pos < (unsigned)BBCAP) bb[pos] = v;
            }
            bcnt += __popc(me);
        }
    }
    __syncwarp();
    const int scnt = (int)min(bcnt, (unsigned)BBCAP);

    // exact ranking inside boundary bin: keep the `need` smallest (ties by index)
    for (int c = lane; c < scnt; c += 32) {
        float vv = bb[c];
        int rank = 0;
        for (int q = 0; q < scnt; q++) {
            float w = bb[q];
            rank += (w < vv) || (w == vv && q < c);
        }
        if (rank < need) esum += pair_energy(vv);
    }

    // warp reduce
#pragma unroll
    for (int off = 16; off; off >>= 1)
        esum += __shfl_down_sync(FULLMASK, esum, off);
    if (lane == 0) warpsum[warp] = esum;
    __syncthreads();

    if (threadIdx.x == 0) {
        float s = 0.0f;
#pragma unroll
        for (int w = 0; w < RPB; w++) s += warpsum[w];
        atomicAdd(&out[b], s);
    }
}

extern "C" void kernel_launch(void* const* d_in, const int* in_sizes, int n_in,
                              void* d_out, int out_size) {
    const float* R = (const float*)d_in[0];
    float* out = (float*)d_out;
    zero_out_kernel<<<1, 32>>>(out);
    repulsion_kernel<<<NBATCH * (LRES / RPB), NTHREADS>>>(R, out);
}

// round 7
// speedup vs baseline: 1.0933x; 1.0933x over previous
#include <cuda_runtime.h>

#define LRES     2048
#define NBATCH   8
#define KSEL     64
#define NBINS    64
#define D2CUT    49.0f          // 7 A cutoff: f(7)=3e-6, dropped tail negligible (measured rel_err 1.3e-7)
#define BINSCALE 1.30612245f    // NBINS / D2CUT
#define CAP      20             // per-lane stack capacity (max expected ~6, 5+ sigma margin)
#define RPB      8
#define NTHREADS 256
#define FULLMASK 0xffffffffu

typedef unsigned long long ull;

// ---- packed f32x2 helpers (SASS FADD2/FMUL2/FFMA2 only reachable via PTX) ----
__device__ __forceinline__ ull pack2(float lo, float hi) {
    ull r; asm("mov.b64 %0, {%1, %2};" : "=l"(r) : "f"(lo), "f"(hi)); return r;
}
__device__ __forceinline__ void unpack2(ull v, float& lo, float& hi) {
    asm("mov.b64 {%0, %1}, %2;" : "=f"(lo), "=f"(hi) : "l"(v));
}
__device__ __forceinline__ ull add2(ull a, ull b) {
    ull r; asm("add.rn.f32x2 %0, %1, %2;" : "=l"(r) : "l"(a), "l"(b)); return r;
}
__device__ __forceinline__ ull mul2(ull a, ull b) {
    ull r; asm("mul.rn.f32x2 %0, %1, %2;" : "=l"(r) : "l"(a), "l"(b)); return r;
}
__device__ __forceinline__ ull fma2(ull a, ull b, ull c) {
    ull r; asm("fma.rn.f32x2 %0, %1, %2, %3;" : "=l"(r) : "l"(a), "l"(b), "l"(c)); return r;
}

__device__ __forceinline__ unsigned warp_incl_scan(unsigned v, int lane) {
#pragma unroll
    for (int off = 1; off < 32; off <<= 1) {
        unsigned u = __shfl_up_sync(FULLMASK, v, off);
        if (lane >= off) v += u;
    }
    return v;
}

// f(d2) = WALL * softplus((R0 - r)/DELTA) * smoothstep_down(r; 8, 10)
__device__ __forceinline__ float pair_energy(float d2) {
    float r  = sqrtf(fmaxf(d2, 1e-12f));
    float t  = (r - 8.0f) * 0.5f;
    t        = fminf(fmaxf(t, 0.0f), 1.0f);
    float sw = 1.0f - t * t * (3.0f - 2.0f * t);
    float x  = (4.0f - r) * 5.0f;
    float sp = (x > 20.0f) ? x : log1pf(expf(x));
    return 10.0f * sp * sw;
}

__global__ void zero_out_kernel(float* out) {
    if (threadIdx.x < NBATCH) out[threadIdx.x] = 0.0f;
}

__global__ __launch_bounds__(NTHREADS)
void repulsion_kernel(const float* __restrict__ R, float* __restrict__ out) {
    __shared__ __align__(16) float sxx[LRES];      //  8192 B  (16B-aligned: legal LDS.64 pairs)
    __shared__ __align__(16) float syy[LRES];      //  8192 B
    __shared__ __align__(16) float szz[LRES];      //  8192 B
    __shared__ float    stack[RPB][CAP][32];       // 20480 B  per-lane stride-32 stacks
    __shared__ unsigned hist[RPB][NBINS];          //  2048 B  (row reused as boundary buf)
    __shared__ unsigned bbcnt[RPB];
    __shared__ float    warpsum[RPB];              // total ~47.2 KB static

    const int blocksPerBatch = LRES / RPB;         // 256
    const int b     = blockIdx.x / blocksPerBatch;
    const int rbase = (blockIdx.x % blocksPerBatch) * RPB;
    const float* Rb = R + (size_t)b * LRES * 3;

    // stage coords into shared (x/y/z planes; consecutive points adjacent -> LDS.64 pairs)
    for (int j = threadIdx.x; j < LRES; j += NTHREADS) {
        sxx[j] = Rb[3 * j + 0];
        syy[j] = Rb[3 * j + 1];
        szz[j] = Rb[3 * j + 2];
    }
    __syncthreads();

    const int warp = threadIdx.x >> 5;
    const int lane = threadIdx.x & 31;
    const int i    = rbase + warp;

    const ull nxi = pack2(-sxx[i], -sxx[i]);
    const ull nyi = pack2(-syy[i], -syy[i]);
    const ull nzi = pack2(-szz[i], -szz[i]);

    const ull* px = (const ull*)sxx;               // pair p -> points (2p, 2p+1)
    const ull* py = (const ull*)syy;
    const ull* pz = (const ull*)szz;

    float* stk  = &stack[warp][0][lane];
    float* sp   = stk;
    float* slim = stk + CAP * 32;

    // ---- hot loop: 16 iterations x 4 points (2 packed pairs) per lane ----
    // pair indices: p0 = 64*it + lane, p1 = p0 + 32; points j0 = 2*p0 = 128*it + 2*lane
    int u = 2 * lane - i + 1;                      // (j - i + 1) for first point
#pragma unroll 4
    for (int it = 0; it < 16; it++) {
        const int p0 = (it << 6) + lane;
        const ull xa = px[p0],      ya = py[p0],      za = pz[p0];
        const ull xb = px[p0 + 32], yb = py[p0 + 32], zb = pz[p0 + 32];

        const ull dxa = add2(xa, nxi), dya = add2(ya, nyi), dza = add2(za, nzi);
        const ull dxb = add2(xb, nxi), dyb = add2(yb, nyi), dzb = add2(zb, nzi);
        const ull d2a = fma2(dza, dza, fma2(dya, dya, mul2(dxa, dxa)));
        const ull d2b = fma2(dzb, dzb, fma2(dyb, dyb, mul2(dxb, dxb)));

        float a0, a1, b0, b1;
        unpack2(d2a, a0, a1);
        unpack2(d2b, b0, b1);

        // keep iff d2 < cutoff and |j-i| >= 2  (u = j-i+1; exclude u in {0,1,2})
        const bool k0 = (a0 < D2CUT) & ((unsigned)(u)      > 2u);
        const bool k1 = (a1 < D2CUT) & ((unsigned)(u + 1)  > 2u);
        const bool k2 = (b0 < D2CUT) & ((unsigned)(u + 64) > 2u);
        const bool k3 = (b1 < D2CUT) & ((unsigned)(u + 65) > 2u);

        if (k0 && sp < slim) { *sp = a0; sp += 32; }
        if (k1 && sp < slim) { *sp = a1; sp += 32; }
        if (k2 && sp < slim) { *sp = b0; sp += 32; }
        if (k3 && sp < slim) { *sp = b1; sp += 32; }
        u += 128;
    }
    const int cnt = (int)((sp - stk) >> 5);

    // ---- epilogue: histogram over tiny per-lane stacks (warp-private) ----
    hist[warp][lane]      = 0;
    hist[warp][lane + 32] = 0;
    if (lane == 0) bbcnt[warp] = 0;
    __syncwarp();
    for (int k = 0; k < cnt; k++) {
        float v = stk[k * 32];
        int bin = min((int)(v * BINSCALE), NBINS - 1);
        atomicAdd(&hist[warp][bin], 1u);
    }
    __syncwarp();

    // cumulative scan over 64 bins (2 chunks of 32)
    unsigned v0 = hist[warp][lane];
    unsigned v1 = hist[warp][lane + 32];
    unsigned c0 = warp_incl_scan(v0, lane);
    unsigned t0 = __shfl_sync(FULLMASK, c0, 31);
    unsigned c1 = warp_incl_scan(v1, lane) + t0;

    // first bin B with cum >= KSEL (NBINS-1 if total < KSEL: keep everything)
    int B = NBINS - 1;
    {
        unsigned m0 = __ballot_sync(FULLMASK, c0 >= (unsigned)KSEL);
        if (m0) B = __ffs(m0) - 1;
        else {
            unsigned m1 = __ballot_sync(FULLMASK, c1 >= (unsigned)KSEL);
            if (m1) B = 32 + __ffs(m1) - 1;
        }
    }
    unsigned cumB = (B < 32) ? __shfl_sync(FULLMASK, c0, B) : __shfl_sync(FULLMASK, c1, B - 32);
    unsigned vB   = (B < 32) ? __shfl_sync(FULLMASK, v0, B) : __shfl_sync(FULLMASK, v1, B - 32);
    const int need = KSEL - (int)(cumB - vB);      // how many to keep from boundary bin
    __syncwarp();                                  // hist values consumed -> row reusable

    // ---- select: bin < B guaranteed top-K; bin == B goes to boundary buffer ----
    float* bb = (float*)hist[warp];                // 64 floats, dead hist storage
    float esum = 0.0f;
    for (int k = 0; k < cnt; k++) {
        float v = stk[k * 32];
        int bin = min((int)(v * BINSCALE), NBINS - 1);
        if (bin < B) esum += pair_energy(v);
        else if (bin == B) {
            unsigned pos = atomicAdd(&bbcnt[warp], 1u);
            if (pos < (unsigned)NBINS) bb[pos] = v;
        }
    }
    __syncwarp();
    const int scnt = (int)min(bbcnt[warp], (unsigned)NBINS);

    // exact ranking inside boundary bin: keep the `need` smallest
    for (int c = lane; c < scnt; c += 32) {
        float vv = bb[c];
        int rank = 0;
        for (int q = 0; q < scnt; q++) {
            float w = bb[q];
            rank += (w < vv) || (w == vv && q < c);
        }
        if (rank < need) esum += pair_energy(vv);
    }

    // warp reduce
#pragma unroll
    for (int off = 16; off; off >>= 1)
        esum += __shfl_down_sync(FULLMASK, esum, off);
    if (lane == 0) warpsum[warp] = esum;
    __syncthreads();

    if (threadIdx.x == 0) {
        float s = 0.0f;
#pragma unroll
        for (int w = 0; w < RPB; w++) s += warpsum[w];
        atomicAdd(&out[b], s);
    }
}

extern "C" void kernel_launch(void* const* d_in, const int* in_sizes, int n_in,
                              void* d_out, int out_size) {
    const float* R = (const float*)d_in[0];
    float* out = (float*)d_out;
    zero_out_kernel<<<1, 32>>>(out);
    repulsion_kernel<<<NBATCH * (LRES / RPB), NTHREADS>>>(R, out);
}

// round 10
// speedup vs baseline: 1.2201x; 1.1159x over previous
#include <cuda_runtime.h>

#define LRES     2048
#define NBATCH   8
#define KSEL     64
#define NBINS    64
#define D2CUT    49.0f          // 7 A cutoff: f(7)=3e-6, tail negligible (measured rel_err ~2e-7)
#define BINSCALE 1.30612245f    // NBINS / D2CUT
#define CAP      20             // per-lane stack capacity (expected max ~6, 5+ sigma margin)
#define RPB      16
#define NTHREADS 512
#define FULLMASK 0xffffffffu

// dynamic smem layout (bytes)
#define OFF_X     0
#define OFF_Y     (OFF_X + LRES * 4)
#define OFF_Z     (OFF_Y + LRES * 4)
#define OFF_STK   (OFF_Z + LRES * 4)                 // RPB*CAP*32 floats
#define OFF_HIST  (OFF_STK + RPB * CAP * 32 * 4)     // RPB*NBINS uints
#define OFF_BBC   (OFF_HIST + RPB * NBINS * 4)       // RPB uints
#define OFF_WSUM  (OFF_BBC + RPB * 4)                // RPB floats
#define SMEM_TOTAL (OFF_WSUM + RPB * 4)              // 69824 B

typedef unsigned long long ull;

// ---- packed f32x2 helpers (SASS FADD2/FMUL2/FFMA2 only reachable via PTX) ----
__device__ __forceinline__ ull pack2(float lo, float hi) {
    ull r; asm("mov.b64 %0, {%1, %2};" : "=l"(r) : "f"(lo), "f"(hi)); return r;
}
__device__ __forceinline__ void unpack2(ull v, float& lo, float& hi) {
    asm("mov.b64 {%0, %1}, %2;" : "=f"(lo), "=f"(hi) : "l"(v));
}
__device__ __forceinline__ ull add2(ull a, ull b) {
    ull r; asm("add.rn.f32x2 %0, %1, %2;" : "=l"(r) : "l"(a), "l"(b)); return r;
}
__device__ __forceinline__ ull mul2(ull a, ull b) {
    ull r; asm("mul.rn.f32x2 %0, %1, %2;" : "=l"(r) : "l"(a), "l"(b)); return r;
}
__device__ __forceinline__ ull fma2(ull a, ull b, ull c) {
    ull r; asm("fma.rn.f32x2 %0, %1, %2, %3;" : "=l"(r) : "l"(a), "l"(b), "l"(c)); return r;
}

__device__ __forceinline__ unsigned warp_incl_scan(unsigned v, int lane) {
#pragma unroll
    for (int off = 1; off < 32; off <<= 1) {
        unsigned u = __shfl_up_sync(FULLMASK, v, off);
        if (lane >= off) v += u;
    }
    return v;
}

// f(d2) = WALL * softplus((R0 - r)/DELTA) * smoothstep_down(r; 8, 10)
__device__ __forceinline__ float pair_energy(float d2) {
    float r  = sqrtf(fmaxf(d2, 1e-12f));
    float t  = (r - 8.0f) * 0.5f;
    t        = fminf(fmaxf(t, 0.0f), 1.0f);
    float sw = 1.0f - t * t * (3.0f - 2.0f * t);
    float x  = (4.0f - r) * 5.0f;
    float sp = (x > 20.0f) ? x : log1pf(expf(x));
    return 10.0f * sp * sw;
}

__global__ void zero_out_kernel(float* out) {
    if (threadIdx.x < NBATCH) out[threadIdx.x] = 0.0f;
}

__global__ __launch_bounds__(NTHREADS)
void repulsion_kernel(const float* __restrict__ R, float* __restrict__ out) {
    extern __shared__ __align__(16) char smem[];
    float*    sxx   = (float*)(smem + OFF_X);
    float*    syy   = (float*)(smem + OFF_Y);
    float*    szz   = (float*)(smem + OFF_Z);
    float*    stack = (float*)(smem + OFF_STK);      // [RPB][CAP][32]
    unsigned* hist  = (unsigned*)(smem + OFF_HIST);  // [RPB][NBINS]
    unsigned* bbcnt = (unsigned*)(smem + OFF_BBC);
    float*    wsum  = (float*)(smem + OFF_WSUM);

    const int blocksPerBatch = LRES / RPB;           // 128
    const int b     = blockIdx.x / blocksPerBatch;
    const int rbase = (blockIdx.x % blocksPerBatch) * RPB;
    const float* Rb = R + (size_t)b * LRES * 3;

    // stage coords into shared (x/y/z planes; consecutive points adjacent -> LDS.64 pairs)
    for (int j = threadIdx.x; j < LRES; j += NTHREADS) {
        sxx[j] = Rb[3 * j + 0];
        syy[j] = Rb[3 * j + 1];
        szz[j] = Rb[3 * j + 2];
    }
    __syncthreads();

    const int warp = threadIdx.x >> 5;
    const int lane = threadIdx.x & 31;
    const int i    = rbase + warp;

    const ull nxi = pack2(-sxx[i], -sxx[i]);
    const ull nyi = pack2(-syy[i], -syy[i]);
    const ull nzi = pack2(-szz[i], -szz[i]);

    const ull* px = (const ull*)sxx;                 // pair p -> points (2p, 2p+1)
    const ull* py = (const ull*)syy;
    const ull* pz = (const ull*)szz;

    float* stk  = stack + warp * (CAP * 32) + lane;
    float* sp   = stk;
    float* slim = stk + CAP * 32;

    // ---- hot loop: 16 iterations x 4 points (2 packed pairs) per lane ----
    int u = 2 * lane - i + 1;                        // (j - i + 1) for first point
#pragma unroll 4
    for (int it = 0; it < 16; it++) {
        const int p0 = (it << 6) + lane;
        const ull xa = px[p0],      ya = py[p0],      za = pz[p0];
        const ull xb = px[p0 + 32], yb = py[p0 + 32], zb = pz[p0 + 32];

        const ull dxa = add2(xa, nxi), dya = add2(ya, nyi), dza = add2(za, nzi);
        const ull dxb = add2(xb, nxi), dyb = add2(yb, nyi), dzb = add2(zb, nzi);
        const ull d2a = fma2(dza, dza, fma2(dya, dya, mul2(dxa, dxa)));
        const ull d2b = fma2(dzb, dzb, fma2(dyb, dyb, mul2(dxb, dxb)));

        float a0, a1, b0, b1;
        unpack2(d2a, a0, a1);
        unpack2(d2b, b0, b1);

        // keep iff d2 < cutoff and |j-i| >= 2  (u = j-i+1; exclude u in {0,1,2})
        const bool k0 = (a0 < D2CUT) & ((unsigned)(u)      > 2u);
        const bool k1 = (a1 < D2CUT) & ((unsigned)(u + 1)  > 2u);
        const bool k2 = (b0 < D2CUT) & ((unsigned)(u + 64) > 2u);
        const bool k3 = (b1 < D2CUT) & ((unsigned)(u + 65) > 2u);

        if (k0 && sp < slim) { *sp = a0; sp += 32; }
        if (k1 && sp < slim) { *sp = a1; sp += 32; }
        if (k2 && sp < slim) { *sp = b0; sp += 32; }
        if (k3 && sp < slim) { *sp = b1; sp += 32; }
        u += 128;
    }
    const int cnt = (int)((sp - stk) >> 5);

    // ---- epilogue: histogram over tiny per-lane stacks (warp-private) ----
    unsigned* h = hist + warp * NBINS;
    h[lane]      = 0;
    h[lane + 32] = 0;
    if (lane == 0) bbcnt[warp] = 0;
    __syncwarp();
    for (int k = 0; k < cnt; k++) {
        float v = stk[k * 32];
        int bin = min((int)(v * BINSCALE), NBINS - 1);
        atomicAdd(&h[bin], 1u);
    }
    __syncwarp();

    // cumulative scan over 64 bins (2 chunks of 32)
    unsigned v0 = h[lane];
    unsigned v1 = h[lane + 32];
    unsigned c0 = warp_incl_scan(v0, lane);
    unsigned t0 = __shfl_sync(FULLMASK, c0, 31);
    unsigned c1 = warp_incl_scan(v1, lane) + t0;

    // first bin B with cum >= KSEL (NBINS-1 if total < KSEL: keep everything)
    int B = NBINS - 1;
    {
        unsigned m0 = __ballot_sync(FULLMASK, c0 >= (unsigned)KSEL);
        if (m0) B = __ffs(m0) - 1;
        else {
            unsigned m1 = __ballot_sync(FULLMASK, c1 >= (unsigned)KSEL);
            if (m1) B = 32 + __ffs(m1) - 1;
        }
    }
    unsigned cumB = (B < 32) ? __shfl_sync(FULLMASK, c0, B) : __shfl_sync(FULLMASK, c1, B - 32);
    unsigned vB   = (B < 32) ? __shfl_sync(FULLMASK, v0, B) : __shfl_sync(FULLMASK, v1, B - 32);
    const int need = KSEL - (int)(cumB - vB);        // how many to keep from boundary bin
    __syncwarp();                                    // hist values consumed -> row reusable

    // ---- select: bin < B guaranteed top-K; bin == B goes to boundary buffer ----
    float* bb = (float*)h;                           // 64 floats, dead hist storage
    float esum = 0.0f;
    for (int k = 0; k < cnt; k++) {
        float v = stk[k * 32];
        int bin = min((int)(v * BINSCALE), NBINS - 1);
        if (bin < B) esum += pair_energy(v);
        else if (bin == B) {
            unsigned pos = atomicAdd(&bbcnt[warp], 1u);
            if (pos < (unsigned)NBINS) bb[pos] = v;
        }
    }
    __syncwarp();
    const int scnt = (int)min(bbcnt[warp], (unsigned)NBINS);

    // exact ranking inside boundary bin: keep the `need` smallest
    for (int c = lane; c < scnt; c += 32) {
        float vv = bb[c];
        int rank = 0;
        for (int q = 0; q < scnt; q++) {
            float w = bb[q];
            rank += (w < vv) || (w == vv && q < c);
        }
        if (rank < need) esum += pair_energy(vv);
    }

    // warp reduce
#pragma unroll
    for (int off = 16; off; off >>= 1)
        esum += __shfl_down_sync(FULLMASK, esum, off);
    if (lane == 0) wsum[warp] = esum;
    __syncthreads();

    if (threadIdx.x == 0) {
        float s = 0.0f;
#pragma unroll
        for (int w = 0; w < RPB; w++) s += wsum[w];
        atomicAdd(&out[b], s);
    }
}

extern "C" void kernel_launch(void* const* d_in, const int* in_sizes, int n_in,
                              void* d_out, int out_size) {
    const float* R = (const float*)d_in[0];
    float* out = (float*)d_out;
    cudaFuncSetAttribute(repulsion_kernel,
                         cudaFuncAttributeMaxDynamicSharedMemorySize, SMEM_TOTAL);
    zero_out_kernel<<<1, 32>>>(out);
    repulsion_kernel<<<NBATCH * (LRES / RPB), NTHREADS, SMEM_TOTAL>>>(R, out);
}